// round 2
// baseline (speedup 1.0000x reference)
#include <cuda_runtime.h>
#include <cstdint>
#include <cstddef>

#define D 128
#define BM 128        // GEMM rows per block
#define KC 32         // GEMM K-chunk
#define XPAD 136      // padded row length for transposed A tile

// Scratch: three [50000 x 128] fp32 ping-pong buffers + BN stat accumulators.
__device__ __align__(16) float g_bufA[50000 * 128];
__device__ __align__(16) float g_bufB[50000 * 128];
__device__ __align__(16) float g_bufC[50000 * 128];
__device__ float g_sums[D];
__device__ float g_sumsq[D];

// ---------------------------------------------------------------------------
// Zero the BN stat accumulators (runs every replay: graph-deterministic)
// ---------------------------------------------------------------------------
__global__ void zero_stats_kernel() {
    if (threadIdx.x < D) {
        g_sums[threadIdx.x] = 0.f;
        g_sumsq[threadIdx.x] = 0.f;
    }
}

// ---------------------------------------------------------------------------
// C[N,128] = act( concat(X1, X2)[N,K] @ W[K,128] + bias )
// X2 == nullptr -> K = 128, else K = 256 (cols 128.. taken from X2).
//
// Block tile 128x128, 256 threads, 8x8 register micro-tile, K-chunk 32.
// A tile stored k-major (XsT[k][row]) so the inner loop is pure float4 LDS:
// per k per thread: 2xfloat4 A + 2xfloat4 B = 32 B LDS for 64 FMA.
// ---------------------------------------------------------------------------
__global__ __launch_bounds__(256) void gemm_kernel(
    const float* __restrict__ X1, const float* __restrict__ X2,
    const float* __restrict__ W, const float* __restrict__ bias,
    float* __restrict__ C, int N, int K, int do_relu)
{
    __shared__ __align__(16) float XsT[KC][XPAD];  // [k][row]
    __shared__ __align__(16) float Ws[KC][D];      // [k][col]

    const int tid = threadIdx.x;
    const int m0  = blockIdx.x * BM;

    // micro-tile coordinates: 16x16 thread grid, each thread 8 rows x 8 cols
    const int rg = (tid >> 4) * 8;   // row group base within block tile
    const int cg = (tid & 15) * 8;   // col group base

    float acc[8][8];
#pragma unroll
    for (int i = 0; i < 8; i++)
#pragma unroll
        for (int j = 0; j < 8; j++) acc[i][j] = 0.f;

    for (int kc = 0; kc < K; kc += KC) {
        const float* src = (kc < D) ? X1 : X2;
        const int    kk  = (kc < D) ? kc : (kc - D);

        // Load X tile (128 rows x 32 k) as float4 along k, store transposed.
        // 128*32/4 = 1024 float4 -> 4 per thread.
#pragma unroll
        for (int i = 0; i < 4; i++) {
            int slot = tid + i * 256;
            int r  = slot >> 3;          // 0..127
            int c4 = (slot & 7) * 4;     // 0..28
            int gr = m0 + r;
            float4 v = make_float4(0.f, 0.f, 0.f, 0.f);
            if (gr < N)
                v = *(const float4*)(src + (size_t)gr * D + kk + c4);
            XsT[c4 + 0][r] = v.x;
            XsT[c4 + 1][r] = v.y;
            XsT[c4 + 2][r] = v.z;
            XsT[c4 + 3][r] = v.w;
        }
        // Load W tile: 32 k x 128 cols = 1024 float4 -> 4 per thread.
#pragma unroll
        for (int i = 0; i < 4; i++) {
            int slot = tid + i * 256;
            int r  = slot >> 5;          // 0..31
            int c4 = (slot & 31) * 4;    // 0..124
            *(float4*)&Ws[r][c4] = *(const float4*)(W + (size_t)(kc + r) * D + c4);
        }
        __syncthreads();

#pragma unroll
        for (int k = 0; k < KC; k++) {
            const float4 a0 = *(const float4*)&XsT[k][rg];
            const float4 a1 = *(const float4*)&XsT[k][rg + 4];
            const float4 b0 = *(const float4*)&Ws[k][cg];
            const float4 b1 = *(const float4*)&Ws[k][cg + 4];
            const float ar[8] = {a0.x, a0.y, a0.z, a0.w, a1.x, a1.y, a1.z, a1.w};
            const float br[8] = {b0.x, b0.y, b0.z, b0.w, b1.x, b1.y, b1.z, b1.w};
#pragma unroll
            for (int i = 0; i < 8; i++)
#pragma unroll
                for (int j = 0; j < 8; j++)
                    acc[i][j] += ar[i] * br[j];
        }
        __syncthreads();
    }

    const float4 bb0 = *(const float4*)(bias + cg);
    const float4 bb1 = *(const float4*)(bias + cg + 4);
    const float br[8] = {bb0.x, bb0.y, bb0.z, bb0.w, bb1.x, bb1.y, bb1.z, bb1.w};

#pragma unroll
    for (int i = 0; i < 8; i++) {
        const int gr = m0 + rg + i;
        if (gr >= N) continue;
        float o[8];
#pragma unroll
        for (int j = 0; j < 8; j++) {
            o[j] = acc[i][j] + br[j];
            if (do_relu) o[j] = fmaxf(o[j], 0.f);
        }
        *(float4*)(C + (size_t)gr * D + cg)     = make_float4(o[0], o[1], o[2], o[3]);
        *(float4*)(C + (size_t)gr * D + cg + 4) = make_float4(o[4], o[5], o[6], o[7]);
    }
}

// ---------------------------------------------------------------------------
// A[n,:] = max over s of Z[neigh[n,s],:]   (warp per node, float4 per lane)
// Z table (25.6 MB) is L2-resident; indices broadcast via shfl.
// ---------------------------------------------------------------------------
__global__ __launch_bounds__(256) void gathermax_kernel(
    const float* __restrict__ Z, const int* __restrict__ nb,
    float* __restrict__ A, int N, int S)
{
    const int w    = (int)((blockIdx.x * (size_t)blockDim.x + threadIdx.x) >> 5);
    const int lane = threadIdx.x & 31;
    if (w >= N) return;

    int idx = 0;
    if (lane < S) idx = nb[(size_t)w * S + lane];

    float4 m = make_float4(-3.402823e38f, -3.402823e38f, -3.402823e38f, -3.402823e38f);
    const int coff = lane * 4;

    if (S == 25) {
#pragma unroll
        for (int s = 0; s < 25; s++) {
            const int j = __shfl_sync(0xffffffffu, idx, s);
            const float4 v = *(const float4*)(Z + (size_t)j * D + coff);
            m.x = fmaxf(m.x, v.x); m.y = fmaxf(m.y, v.y);
            m.z = fmaxf(m.z, v.z); m.w = fmaxf(m.w, v.w);
        }
    } else {
        for (int s = 0; s < S; s++) {
            const int j = __shfl_sync(0xffffffffu, idx, s);
            const float4 v = *(const float4*)(Z + (size_t)j * D + coff);
            m.x = fmaxf(m.x, v.x); m.y = fmaxf(m.y, v.y);
            m.z = fmaxf(m.z, v.z); m.w = fmaxf(m.w, v.w);
        }
    }
    *(float4*)(A + (size_t)w * D + coff) = m;
}

// ---------------------------------------------------------------------------
// BN column stats: per-thread partial sums over strided rows, atomic combine.
// ---------------------------------------------------------------------------
__global__ __launch_bounds__(128) void bn_stats_kernel(const float* __restrict__ Y, int N)
{
    const int d = threadIdx.x;
    float s = 0.f, s2 = 0.f;
    for (int r = blockIdx.x; r < N; r += gridDim.x) {
        const float v = Y[(size_t)r * D + d];
        s  += v;
        s2 += v * v;
    }
    atomicAdd(&g_sums[d], s);
    atomicAdd(&g_sumsq[d], s2);
}

// ---------------------------------------------------------------------------
// BatchNorm (batch stats) + row L2 normalize. Warp per row.
// ---------------------------------------------------------------------------
__global__ __launch_bounds__(256) void bn_norm_kernel(
    const float* __restrict__ Y, const float* __restrict__ gamma,
    const float* __restrict__ beta, float* __restrict__ Xo, int N, float invN)
{
    const int w    = (int)((blockIdx.x * (size_t)blockDim.x + threadIdx.x) >> 5);
    const int lane = threadIdx.x & 31;
    if (w >= N) return;
    const int c = lane * 4;

    const float4 y  = *(const float4*)(Y + (size_t)w * D + c);
    const float4 sm = *(const float4*)(g_sums + c);
    const float4 sq = *(const float4*)(g_sumsq + c);
    const float4 g  = *(const float4*)(gamma + c);
    const float4 b  = *(const float4*)(beta + c);

    float xn[4];
    {
        float mu, var;
        mu = sm.x * invN; var = sq.x * invN - mu * mu;
        xn[0] = (y.x - mu) * rsqrtf(var + 1e-5f) * g.x + b.x;
        mu = sm.y * invN; var = sq.y * invN - mu * mu;
        xn[1] = (y.y - mu) * rsqrtf(var + 1e-5f) * g.y + b.y;
        mu = sm.z * invN; var = sq.z * invN - mu * mu;
        xn[2] = (y.z - mu) * rsqrtf(var + 1e-5f) * g.z + b.z;
        mu = sm.w * invN; var = sq.w * invN - mu * mu;
        xn[3] = (y.w - mu) * rsqrtf(var + 1e-5f) * g.w + b.w;
    }

    float ss = xn[0] * xn[0] + xn[1] * xn[1] + xn[2] * xn[2] + xn[3] * xn[3];
#pragma unroll
    for (int o = 16; o > 0; o >>= 1)
        ss += __shfl_xor_sync(0xffffffffu, ss, o);

    const float inv = 1.f / (sqrtf(ss) + 1e-6f);
    float4 o4;
    o4.x = xn[0] * inv; o4.y = xn[1] * inv; o4.z = xn[2] * inv; o4.w = xn[3] * inv;
    *(float4*)(Xo + (size_t)w * D + c) = o4;
}

// ---------------------------------------------------------------------------
// Launch
// ---------------------------------------------------------------------------
extern "C" void kernel_launch(void* const* d_in, const int* in_sizes, int n_in,
                              void* d_out, int out_size)
{
    const float* X    = (const float*)d_in[0];
    const int*   n0   = (const int*)  d_in[1];
    const int*   n1   = (const int*)  d_in[2];
    const float* Wa0  = (const float*)d_in[3];
    const float* ba0  = (const float*)d_in[4];
    const float* Wa1  = (const float*)d_in[5];
    const float* ba1  = (const float*)d_in[6];
    const float* W0   = (const float*)d_in[7];
    const float* b0   = (const float*)d_in[8];
    const float* W1   = (const float*)d_in[9];
    const float* b1   = (const float*)d_in[10];
    const float* gmm  = (const float*)d_in[11];
    const float* beta = (const float*)d_in[12];

    const int N = in_sizes[0] / D;
    const int S = in_sizes[1] / N;

    float *A, *B, *C;
    cudaGetSymbolAddress((void**)&A, g_bufA);
    cudaGetSymbolAddress((void**)&B, g_bufB);
    cudaGetSymbolAddress((void**)&C, g_bufC);

    const int gemm_blocks = (N + BM - 1) / BM;
    const int warp_blocks = (N + 7) / 8;

    // ---- Layer 0 ----
    // Z0 = relu(X @ Wa0 + ba0)   [linearity: aggregate AFTER the GEMM, 25x FLOP cut]
    gemm_kernel<<<gemm_blocks, 256>>>(X, nullptr, Wa0, ba0, A, N, D, 1);
    // agg0 = max_s Z0[neigh0]
    gathermax_kernel<<<warp_blocks, 256>>>(A, n0, B, N, S);
    // Y = relu([X, agg0] @ W0 + b0)
    gemm_kernel<<<gemm_blocks, 256>>>(X, B, W0, b0, C, N, 2 * D, 1);
    // BatchNorm batch stats + row L2 normalize -> X1 (in A)
    zero_stats_kernel<<<1, 128>>>();
    bn_stats_kernel<<<250, 128>>>(C, N);
    bn_norm_kernel<<<warp_blocks, 256>>>(C, gmm, beta, A, N, 1.f / (float)N);

    // ---- Layer 1 ----
    // Z1 = relu(X1 @ Wa1 + ba1)
    gemm_kernel<<<gemm_blocks, 256>>>(A, nullptr, Wa1, ba1, C, N, D, 1);
    // agg1 = max_s Z1[neigh1]
    gathermax_kernel<<<warp_blocks, 256>>>(C, n1, B, N, S);
    // out = [X1, agg1] @ W1 + b1   (no activation)
    gemm_kernel<<<gemm_blocks, 256>>>(A, B, W1, b1, (float*)d_out, N, 2 * D, 0);
}

// round 4
// speedup vs baseline: 1.5061x; 1.5061x over previous
#include <cuda_runtime.h>
#include <cstdint>
#include <cstddef>

#define D 128
#define BM 128        // GEMM rows per block
#define KCH 32        // GEMM K-chunk (4 k8 steps)

// Scratch: three [50000 x 128] fp32 ping-pong buffers + BN stat accumulators.
__device__ __align__(16) float g_bufA[50000 * 128];
__device__ __align__(16) float g_bufB[50000 * 128];
__device__ __align__(16) float g_bufC[50000 * 128];
__device__ float g_sums[D];
__device__ float g_sumsq[D];

__device__ __forceinline__ uint32_t f2tf32(float x) {
    uint32_t u;
    asm("cvt.rna.tf32.f32 %0, %1;" : "=r"(u) : "f"(x));
    return u;
}

__device__ __forceinline__ void mma_tf32(float* c, const uint32_t* a, const uint32_t* b) {
    asm volatile(
        "mma.sync.aligned.m16n8k8.row.col.f32.tf32.tf32.f32 "
        "{%0,%1,%2,%3}, {%4,%5,%6,%7}, {%8,%9}, {%0,%1,%2,%3};"
        : "+f"(c[0]), "+f"(c[1]), "+f"(c[2]), "+f"(c[3])
        : "r"(a[0]), "r"(a[1]), "r"(a[2]), "r"(a[3]), "r"(b[0]), "r"(b[1]));
}

// ---------------------------------------------------------------------------
// Zero the BN stat accumulators (runs every replay: graph-deterministic)
// ---------------------------------------------------------------------------
__global__ void zero_stats_kernel() {
    if (threadIdx.x < D) {
        g_sums[threadIdx.x] = 0.f;
        g_sumsq[threadIdx.x] = 0.f;
    }
}

// ---------------------------------------------------------------------------
// C[N,128] = act( concat(X1, X2)[N,K] @ W[K,128] + bias )   -- TF32 tensor core
// X2 == nullptr -> K = 128, else K = 256 (cols 128.. taken from X2).
//
// Block tile 128x128, 256 threads = 8 warps in a 2(M) x 4(N) grid;
// warp tile 64x32 = 4x4 mma tiles of m16n8k8. K staged in 32-chunks with
// register prefetch. Smem holds fragments in per-lane layout so the mainloop
// does only conflict-free LDS.128 / LDS.64.
// ---------------------------------------------------------------------------
__global__ __launch_bounds__(256) void gemm_tf32_kernel(
    const float* __restrict__ X1, const float* __restrict__ X2,
    const float* __restrict__ W, const float* __restrict__ bias,
    float* __restrict__ C, int N, int K, int do_relu)
{
    // A fragments: [m16 tile 0..7][kt 0..3][lane][4 vals]
    __shared__ uint32_t Af[8][4][32][4];
    // B fragments: [kt 0..3][n8 tile 0..15][lane][2 vals]
    __shared__ uint32_t Bf[4][16][32][2];

    const int tid  = threadIdx.x;
    const int lane = tid & 31;
    const int wid  = tid >> 5;
    const int wM   = wid >> 2;        // 0..1 -> M offset wM*64
    const int wN   = wid & 3;         // 0..3 -> N offset wN*32
    const int g    = lane >> 2;       // fragment group 0..7
    const int tg   = lane & 3;        // thread-in-group 0..3
    const int m0   = blockIdx.x * BM;

    // Per-thread staging coordinates.
    // A: 128 rows x 32 cols = 4096 floats -> 16 per thread (4 float4).
    const int ar  = tid >> 1;              // A: row 0..127
    const int ab  = (tid & 1) * 16;        // A: col base {0,16}, 4 float4
    // B: 32 k x 128 cols = 4096 floats -> 16 per thread (4 float4).
    const int bk  = tid >> 3;              // B: k row 0..31
    const int bc4 = (tid & 7) * 16;        // B: col base, 4 float4

    float4 ra[4], rb[4];
    const int nchunk = K / KCH;

    // ---- global load of chunk c into registers ----
    auto load_chunk = [&](int c) {
        const float* src = (c * KCH < D) ? X1 : X2;
        const int    kk  = (c * KCH < D) ? c * KCH : c * KCH - D;
        const int    gr  = m0 + ar;
        if (gr < N) {
#pragma unroll
            for (int h = 0; h < 4; h++)
                ra[h] = *(const float4*)(src + (size_t)gr * D + kk + ab + h * 4);
        } else {
#pragma unroll
            for (int h = 0; h < 4; h++)
                ra[h] = make_float4(0.f, 0.f, 0.f, 0.f);
        }
        const float* wrow = W + (size_t)(c * KCH + bk) * D + bc4;
#pragma unroll
        for (int h = 0; h < 4; h++)
            rb[h] = *(const float4*)(wrow + h * 4);
    };

    // ---- scatter registers into fragment-major smem ----
    auto stage_chunk = [&]() {
        const int mt  = ar >> 4;
        const int r16 = ar & 15;
        const int ga  = r16 & 7;
        const int vh  = r16 >> 3;          // 0: rows 0-7 of m16, 1: rows 8-15
#pragma unroll
        for (int h = 0; h < 4; h++) {
            const int c4 = ab + h * 4;     // col in chunk: 0..28 step 4
            const int kt = c4 >> 3;        // k8 tile 0..3
            const int ch = (c4 >> 2) & 1;  // 0: cols 0-3 of k8, 1: cols 4-7
            const float* v = (const float*)&ra[h];
#pragma unroll
            for (int j = 0; j < 4; j++)
                Af[mt][kt][ga * 4 + j][ch * 2 + vh] = f2tf32(v[j]);
        }
        const int kt  = bk >> 3;
        const int k8  = bk & 7;
        const int btg = k8 & 3;
        const int bv  = k8 >> 2;
#pragma unroll
        for (int h = 0; h < 4; h++) {
            const float* v = (const float*)&rb[h];
#pragma unroll
            for (int j = 0; j < 4; j++) {
                const int col = bc4 + h * 4 + j;
                Bf[kt][col >> 3][(col & 7) * 4 + btg][bv] = f2tf32(v[j]);
            }
        }
    };

    float acc[4][4][4];
#pragma unroll
    for (int mt = 0; mt < 4; mt++)
#pragma unroll
        for (int nt = 0; nt < 4; nt++)
#pragma unroll
            for (int i = 0; i < 4; i++) acc[mt][nt][i] = 0.f;

    load_chunk(0);
    stage_chunk();
    __syncthreads();

    for (int c = 0; c < nchunk; c++) {
        if (c + 1 < nchunk) load_chunk(c + 1);

#pragma unroll
        for (int kt = 0; kt < 4; kt++) {
            uint32_t a[4][4], b[4][2];
#pragma unroll
            for (int mt = 0; mt < 4; mt++) {
                const uint4 va = *(const uint4*)Af[wM * 4 + mt][kt][lane];
                a[mt][0] = va.x; a[mt][1] = va.y; a[mt][2] = va.z; a[mt][3] = va.w;
            }
#pragma unroll
            for (int nt = 0; nt < 4; nt++) {
                const uint2 vb = *(const uint2*)Bf[kt][wN * 4 + nt][lane];
                b[nt][0] = vb.x; b[nt][1] = vb.y;
            }
#pragma unroll
            for (int mt = 0; mt < 4; mt++)
#pragma unroll
                for (int nt = 0; nt < 4; nt++)
                    mma_tf32(acc[mt][nt], a[mt], b[nt]);
        }

        if (c + 1 < nchunk) {
            __syncthreads();
            stage_chunk();
            __syncthreads();
        }
    }

    // ---- epilogue: bias (+relu), write fp32 ----
#pragma unroll
    for (int nt = 0; nt < 4; nt++) {
        const int colb = wN * 32 + nt * 8 + 2 * tg;
        const float2 bb = *(const float2*)(bias + colb);
#pragma unroll
        for (int mt = 0; mt < 4; mt++) {
            const int row0 = m0 + wM * 64 + mt * 16 + g;
            float2 o0, o1;
            o0.x = acc[mt][nt][0] + bb.x;
            o0.y = acc[mt][nt][1] + bb.y;
            o1.x = acc[mt][nt][2] + bb.x;
            o1.y = acc[mt][nt][3] + bb.y;
            if (do_relu) {
                o0.x = fmaxf(o0.x, 0.f); o0.y = fmaxf(o0.y, 0.f);
                o1.x = fmaxf(o1.x, 0.f); o1.y = fmaxf(o1.y, 0.f);
            }
            if (row0 < N)     *(float2*)(C + (size_t)row0 * D + colb)       = o0;
            if (row0 + 8 < N) *(float2*)(C + (size_t)(row0 + 8) * D + colb) = o1;
        }
    }
}

// ---------------------------------------------------------------------------
// A[n,:] = max over s of Z[neigh[n,s],:]   (warp per node, float4 per lane)
// ---------------------------------------------------------------------------
__global__ __launch_bounds__(256) void gathermax_kernel(
    const float* __restrict__ Z, const int* __restrict__ nb,
    float* __restrict__ A, int N, int S)
{
    const int w    = (int)((blockIdx.x * (size_t)blockDim.x + threadIdx.x) >> 5);
    const int lane = threadIdx.x & 31;
    if (w >= N) return;

    int idx = 0;
    if (lane < S) idx = nb[(size_t)w * S + lane];

    float4 m = make_float4(-3.402823e38f, -3.402823e38f, -3.402823e38f, -3.402823e38f);
    const int coff = lane * 4;

    if (S == 25) {
#pragma unroll
        for (int s = 0; s < 25; s++) {
            const int j = __shfl_sync(0xffffffffu, idx, s);
            const float4 v = *(const float4*)(Z + (size_t)j * D + coff);
            m.x = fmaxf(m.x, v.x); m.y = fmaxf(m.y, v.y);
            m.z = fmaxf(m.z, v.z); m.w = fmaxf(m.w, v.w);
        }
    } else {
        for (int s = 0; s < S; s++) {
            const int j = __shfl_sync(0xffffffffu, idx, s);
            const float4 v = *(const float4*)(Z + (size_t)j * D + coff);
            m.x = fmaxf(m.x, v.x); m.y = fmaxf(m.y, v.y);
            m.z = fmaxf(m.z, v.z); m.w = fmaxf(m.w, v.w);
        }
    }
    *(float4*)(A + (size_t)w * D + coff) = m;
}

// ---------------------------------------------------------------------------
// BN column stats: per-thread partial sums over strided rows, atomic combine.
// ---------------------------------------------------------------------------
__global__ __launch_bounds__(128) void bn_stats_kernel(const float* __restrict__ Y, int N)
{
    const int d = threadIdx.x;
    float s = 0.f, s2 = 0.f;
    for (int r = blockIdx.x; r < N; r += gridDim.x) {
        const float v = Y[(size_t)r * D + d];
        s  += v;
        s2 += v * v;
    }
    atomicAdd(&g_sums[d], s);
    atomicAdd(&g_sumsq[d], s2);
}

// ---------------------------------------------------------------------------
// BatchNorm (batch stats) + row L2 normalize. Warp per row.
// ---------------------------------------------------------------------------
__global__ __launch_bounds__(256) void bn_norm_kernel(
    const float* __restrict__ Y, const float* __restrict__ gamma,
    const float* __restrict__ beta, float* __restrict__ Xo, int N, float invN)
{
    const int w    = (int)((blockIdx.x * (size_t)blockDim.x + threadIdx.x) >> 5);
    const int lane = threadIdx.x & 31;
    if (w >= N) return;
    const int c = lane * 4;

    const float4 y  = *(const float4*)(Y + (size_t)w * D + c);
    const float4 sm = *(const float4*)(g_sums + c);
    const float4 sq = *(const float4*)(g_sumsq + c);
    const float4 g  = *(const float4*)(gamma + c);
    const float4 b  = *(const float4*)(beta + c);

    float xn[4];
    {
        float mu, var;
        mu = sm.x * invN; var = sq.x * invN - mu * mu;
        xn[0] = (y.x - mu) * rsqrtf(var + 1e-5f) * g.x + b.x;
        mu = sm.y * invN; var = sq.y * invN - mu * mu;
        xn[1] = (y.y - mu) * rsqrtf(var + 1e-5f) * g.y + b.y;
        mu = sm.z * invN; var = sq.z * invN - mu * mu;
        xn[2] = (y.z - mu) * rsqrtf(var + 1e-5f) * g.z + b.z;
        mu = sm.w * invN; var = sq.w * invN - mu * mu;
        xn[3] = (y.w - mu) * rsqrtf(var + 1e-5f) * g.w + b.w;
    }

    float ss = xn[0] * xn[0] + xn[1] * xn[1] + xn[2] * xn[2] + xn[3] * xn[3];
#pragma unroll
    for (int o = 16; o > 0; o >>= 1)
        ss += __shfl_xor_sync(0xffffffffu, ss, o);

    const float inv = 1.f / (sqrtf(ss) + 1e-6f);
    float4 o4;
    o4.x = xn[0] * inv; o4.y = xn[1] * inv; o4.z = xn[2] * inv; o4.w = xn[3] * inv;
    *(float4*)(Xo + (size_t)w * D + c) = o4;
}

// ---------------------------------------------------------------------------
// Launch
// ---------------------------------------------------------------------------
extern "C" void kernel_launch(void* const* d_in, const int* in_sizes, int n_in,
                              void* d_out, int out_size)
{
    const float* X    = (const float*)d_in[0];
    const int*   n0   = (const int*)  d_in[1];
    const int*   n1   = (const int*)  d_in[2];
    const float* Wa0  = (const float*)d_in[3];
    const float* ba0  = (const float*)d_in[4];
    const float* Wa1  = (const float*)d_in[5];
    const float* ba1  = (const float*)d_in[6];
    const float* W0   = (const float*)d_in[7];
    const float* b0   = (const float*)d_in[8];
    const float* W1   = (const float*)d_in[9];
    const float* b1   = (const float*)d_in[10];
    const float* gmm  = (const float*)d_in[11];
    const float* beta = (const float*)d_in[12];

    const int N = in_sizes[0] / D;
    const int S = in_sizes[1] / N;

    float *A, *B, *C;
    cudaGetSymbolAddress((void**)&A, g_bufA);
    cudaGetSymbolAddress((void**)&B, g_bufB);
    cudaGetSymbolAddress((void**)&C, g_bufC);

    const int gemm_blocks = (N + BM - 1) / BM;
    const int warp_blocks = (N + 7) / 8;

    // ---- Layer 0 ----
    // Z0 = relu(X @ Wa0 + ba0)   [linearity: aggregate AFTER the GEMM, 25x FLOP cut]
    gemm_tf32_kernel<<<gemm_blocks, 256>>>(X, nullptr, Wa0, ba0, A, N, D, 1);
    // agg0 = max_s Z0[neigh0]
    gathermax_kernel<<<warp_blocks, 256>>>(A, n0, B, N, S);
    // Y = relu([X, agg0] @ W0 + b0)
    gemm_tf32_kernel<<<gemm_blocks, 256>>>(X, B, W0, b0, C, N, 2 * D, 1);
    // BatchNorm batch stats + row L2 normalize -> X1 (in A)
    zero_stats_kernel<<<1, 128>>>();
    bn_stats_kernel<<<250, 128>>>(C, N);
    bn_norm_kernel<<<warp_blocks, 256>>>(C, gmm, beta, A, N, 1.f / (float)N);

    // ---- Layer 1 ----
    // Z1 = relu(X1 @ Wa1 + ba1)
    gemm_tf32_kernel<<<gemm_blocks, 256>>>(A, nullptr, Wa1, ba1, C, N, D, 1);
    // agg1 = max_s Z1[neigh1]
    gathermax_kernel<<<warp_blocks, 256>>>(C, n1, B, N, S);
    // out = [X1, agg1] @ W1 + b1   (no activation)
    gemm_tf32_kernel<<<gemm_blocks, 256>>>(A, B, W1, b1, (float*)d_out, N, 2 * D, 0);
}

// round 5
// speedup vs baseline: 1.7658x; 1.1724x over previous
#include <cuda_runtime.h>
#include <cstdint>
#include <cstddef>

#define D 128
#define BM 128        // GEMM rows per block
#define KCH 32        // GEMM K-chunk (4 k8 steps)

// Dynamic smem layout (uint32 units), double buffered:
//   Af stage s: [8 mt][4 kt][32 lane][4]  -> 4096 u32 per stage
//   Bf stage s: [4 kt][16 n8][32 lane][2] -> 4096 u32 per stage
#define AF_STG 4096
#define BF_BASE 8192
#define SMEM_BYTES (16384 * 4)

// Scratch: three [50000 x 128] fp32 ping-pong buffers + BN stat accumulators.
__device__ __align__(16) float g_bufA[50000 * 128];
__device__ __align__(16) float g_bufB[50000 * 128];
__device__ __align__(16) float g_bufC[50000 * 128];
__device__ float g_sums[D];
__device__ float g_sumsq[D];

__device__ __forceinline__ uint32_t f2tf32(float x) {
    uint32_t u;
    asm("cvt.rna.tf32.f32 %0, %1;" : "=r"(u) : "f"(x));
    return u;
}

__device__ __forceinline__ void mma_tf32(float* c, const uint32_t* a, const uint32_t* b) {
    asm volatile(
        "mma.sync.aligned.m16n8k8.row.col.f32.tf32.tf32.f32 "
        "{%0,%1,%2,%3}, {%4,%5,%6,%7}, {%8,%9}, {%0,%1,%2,%3};"
        : "+f"(c[0]), "+f"(c[1]), "+f"(c[2]), "+f"(c[3])
        : "r"(a[0]), "r"(a[1]), "r"(a[2]), "r"(a[3]), "r"(b[0]), "r"(b[1]));
}

// ---------------------------------------------------------------------------
// C[N,128] = act( concat(X1, X2)[N,K] @ W[K,128] + bias )   -- TF32 tensor core
// MODE 0: plain.  MODE 1: one extra grid block zeroes BN stat accumulators.
// MODE 2: epilogue also accumulates post-relu column sum/sumsq into g_sums/q.
//
// 128x128 block tile, 8 warps (2M x 4N), warp tile 64x32 (4x4 m16n8k8),
// K in 32-chunks, double-buffered fragment-major smem: one sync per chunk,
// next chunk's staging STS overlap current chunk's MMAs.
// ---------------------------------------------------------------------------
template <int MODE>
__global__ __launch_bounds__(256) void gemm_tf32_kernel(
    const float* __restrict__ X1, const float* __restrict__ X2,
    const float* __restrict__ W, const float* __restrict__ bias,
    float* __restrict__ C, int N, int K, int do_relu)
{
    extern __shared__ uint32_t dynsmem[];

    if (MODE == 1 && blockIdx.x == gridDim.x - 1) {
        if (threadIdx.x < D) {
            g_sums[threadIdx.x] = 0.f;
            g_sumsq[threadIdx.x] = 0.f;
        }
        return;
    }

    const int tid  = threadIdx.x;
    const int lane = tid & 31;
    const int wid  = tid >> 5;
    const int wM   = wid >> 2;        // 0..1 -> M offset wM*64
    const int wN   = wid & 3;         // 0..3 -> N offset wN*32
    const int g    = lane >> 2;       // fragment group 0..7
    const int tg   = lane & 3;        // thread-in-group 0..3
    const int m0   = blockIdx.x * BM;

    // Per-thread staging coordinates.
    const int ar  = tid >> 1;              // A: row 0..127, 16 floats each
    const int ab  = (tid & 1) * 16;        // A: col base {0,16}
    const int bk  = tid >> 3;              // B: k row 0..31, 16 floats each
    const int bc4 = (tid & 7) * 16;        // B: col base

    float4 ra[4], rb[4];
    const int nchunk = K / KCH;

    auto load_chunk = [&](int c) {
        const float* src = (c * KCH < D) ? X1 : X2;
        const int    kk  = (c * KCH < D) ? c * KCH : c * KCH - D;
        const int    gr  = m0 + ar;
        if (gr < N) {
#pragma unroll
            for (int h = 0; h < 4; h++)
                ra[h] = *(const float4*)(src + (size_t)gr * D + kk + ab + h * 4);
        } else {
#pragma unroll
            for (int h = 0; h < 4; h++)
                ra[h] = make_float4(0.f, 0.f, 0.f, 0.f);
        }
        const float* wrow = W + (size_t)(c * KCH + bk) * D + bc4;
#pragma unroll
        for (int h = 0; h < 4; h++)
            rb[h] = *(const float4*)(wrow + h * 4);
    };

    auto stage_chunk = [&](int s) {
        uint32_t* Afs = dynsmem + s * AF_STG;
        uint32_t* Bfs = dynsmem + BF_BASE + s * AF_STG;
        const int mt  = ar >> 4;
        const int r16 = ar & 15;
        const int ga  = r16 & 7;
        const int vh  = r16 >> 3;
#pragma unroll
        for (int h = 0; h < 4; h++) {
            const int c4 = ab + h * 4;
            const int kt = c4 >> 3;
            const int ch = (c4 >> 2) & 1;
            const float* v = (const float*)&ra[h];
#pragma unroll
            for (int j = 0; j < 4; j++)
                Afs[(((mt * 4 + kt) * 32) + ga * 4 + j) * 4 + ch * 2 + vh] = f2tf32(v[j]);
        }
        const int kt  = bk >> 3;
        const int k8  = bk & 7;
        const int btg = k8 & 3;
        const int bv  = k8 >> 2;
#pragma unroll
        for (int h = 0; h < 4; h++) {
            const float* v = (const float*)&rb[h];
#pragma unroll
            for (int j = 0; j < 4; j++) {
                const int col = bc4 + h * 4 + j;
                Bfs[(((kt * 16 + (col >> 3)) * 32) + (col & 7) * 4 + btg) * 2 + bv] = f2tf32(v[j]);
            }
        }
    };

    float acc[4][4][4];
#pragma unroll
    for (int mt = 0; mt < 4; mt++)
#pragma unroll
        for (int nt = 0; nt < 4; nt++)
#pragma unroll
            for (int i = 0; i < 4; i++) acc[mt][nt][i] = 0.f;

    load_chunk(0);
    stage_chunk(0);
    __syncthreads();

    for (int c = 0; c < nchunk; c++) {
        const int s = c & 1;
        if (c + 1 < nchunk) load_chunk(c + 1);   // LDG in flight during MMAs

        const uint32_t* Afs = dynsmem + s * AF_STG;
        const uint32_t* Bfs = dynsmem + BF_BASE + s * AF_STG;
#pragma unroll
        for (int kt = 0; kt < 4; kt++) {
            uint32_t a[4][4], b[4][2];
#pragma unroll
            for (int mt = 0; mt < 4; mt++) {
                const uint4 va = *(const uint4*)&Afs[((((wM * 4 + mt) * 4 + kt) * 32) + lane) * 4];
                a[mt][0] = va.x; a[mt][1] = va.y; a[mt][2] = va.z; a[mt][3] = va.w;
            }
#pragma unroll
            for (int nt = 0; nt < 4; nt++) {
                const uint2 vb = *(const uint2*)&Bfs[(((kt * 16 + wN * 4 + nt) * 32) + lane) * 2];
                b[nt][0] = vb.x; b[nt][1] = vb.y;
            }
#pragma unroll
            for (int mt = 0; mt < 4; mt++)
#pragma unroll
                for (int nt = 0; nt < 4; nt++)
                    mma_tf32(acc[mt][nt], a[mt], b[nt]);
        }

        if (c + 1 < nchunk) {
            stage_chunk(s ^ 1);     // STS overlap the in-flight MMAs
            __syncthreads();
        }
    }

    // ---- epilogue: bias (+relu), optional BN stats, write fp32 ----
    float cs[8], cq[8];
    if (MODE == 2) {
#pragma unroll
        for (int i = 0; i < 8; i++) { cs[i] = 0.f; cq[i] = 0.f; }
    }

#pragma unroll
    for (int nt = 0; nt < 4; nt++) {
        const int colb = wN * 32 + nt * 8 + 2 * tg;
        const float2 bb = *(const float2*)(bias + colb);
#pragma unroll
        for (int mt = 0; mt < 4; mt++) {
            const int row0 = m0 + wM * 64 + mt * 16 + g;
            float2 o0, o1;
            o0.x = acc[mt][nt][0] + bb.x;
            o0.y = acc[mt][nt][1] + bb.y;
            o1.x = acc[mt][nt][2] + bb.x;
            o1.y = acc[mt][nt][3] + bb.y;
            if (do_relu) {
                o0.x = fmaxf(o0.x, 0.f); o0.y = fmaxf(o0.y, 0.f);
                o1.x = fmaxf(o1.x, 0.f); o1.y = fmaxf(o1.y, 0.f);
            }
            const bool v0 = row0 < N, v1 = row0 + 8 < N;
            if (MODE == 2) {
                if (v0) {
                    cs[nt * 2]     += o0.x;  cq[nt * 2]     += o0.x * o0.x;
                    cs[nt * 2 + 1] += o0.y;  cq[nt * 2 + 1] += o0.y * o0.y;
                }
                if (v1) {
                    cs[nt * 2]     += o1.x;  cq[nt * 2]     += o1.x * o1.x;
                    cs[nt * 2 + 1] += o1.y;  cq[nt * 2 + 1] += o1.y * o1.y;
                }
            }
            if (v0) *(float2*)(C + (size_t)row0 * D + colb)       = o0;
            if (v1) *(float2*)(C + (size_t)(row0 + 8) * D + colb) = o1;
        }
    }

    if (MODE == 2) {
        // reduce over g (lane bits 2..4), then lanes 0..3 hold (tg) totals
#pragma unroll
        for (int o = 4; o < 32; o <<= 1) {
#pragma unroll
            for (int i = 0; i < 8; i++) {
                cs[i] += __shfl_xor_sync(0xffffffffu, cs[i], o);
                cq[i] += __shfl_xor_sync(0xffffffffu, cq[i], o);
            }
        }
        if (g == 0) {
#pragma unroll
            for (int i = 0; i < 8; i++) {
                const int col = wN * 32 + (i >> 1) * 8 + 2 * tg + (i & 1);
                atomicAdd(&g_sums[col], cs[i]);
                atomicAdd(&g_sumsq[col], cq[i]);
            }
        }
    }
}

// ---------------------------------------------------------------------------
// A[n,:] = max over s of Z[neigh[n,s],:]   (warp per node, float4 per lane)
// ---------------------------------------------------------------------------
__global__ __launch_bounds__(256) void gathermax_kernel(
    const float* __restrict__ Z, const int* __restrict__ nb,
    float* __restrict__ A, int N, int S)
{
    const int w    = (int)((blockIdx.x * (size_t)blockDim.x + threadIdx.x) >> 5);
    const int lane = threadIdx.x & 31;
    if (w >= N) return;

    int idx = 0;
    if (lane < S) idx = nb[(size_t)w * S + lane];

    float4 m = make_float4(-3.402823e38f, -3.402823e38f, -3.402823e38f, -3.402823e38f);
    const int coff = lane * 4;

    if (S == 25) {
#pragma unroll
        for (int s = 0; s < 25; s++) {
            const int j = __shfl_sync(0xffffffffu, idx, s);
            const float4 v = *(const float4*)(Z + (size_t)j * D + coff);
            m.x = fmaxf(m.x, v.x); m.y = fmaxf(m.y, v.y);
            m.z = fmaxf(m.z, v.z); m.w = fmaxf(m.w, v.w);
        }
    } else {
        for (int s = 0; s < S; s++) {
            const int j = __shfl_sync(0xffffffffu, idx, s);
            const float4 v = *(const float4*)(Z + (size_t)j * D + coff);
            m.x = fmaxf(m.x, v.x); m.y = fmaxf(m.y, v.y);
            m.z = fmaxf(m.z, v.z); m.w = fmaxf(m.w, v.w);
        }
    }
    *(float4*)(A + (size_t)w * D + coff) = m;
}

// ---------------------------------------------------------------------------
// BatchNorm (batch stats) + row L2 normalize. Warp per row.
// ---------------------------------------------------------------------------
__global__ __launch_bounds__(256) void bn_norm_kernel(
    const float* __restrict__ Y, const float* __restrict__ gamma,
    const float* __restrict__ beta, float* __restrict__ Xo, int N, float invN)
{
    const int w    = (int)((blockIdx.x * (size_t)blockDim.x + threadIdx.x) >> 5);
    const int lane = threadIdx.x & 31;
    if (w >= N) return;
    const int c = lane * 4;

    const float4 y  = *(const float4*)(Y + (size_t)w * D + c);
    const float4 sm = *(const float4*)(g_sums + c);
    const float4 sq = *(const float4*)(g_sumsq + c);
    const float4 g  = *(const float4*)(gamma + c);
    const float4 b  = *(const float4*)(beta + c);

    float xn[4];
    {
        float mu, var;
        mu = sm.x * invN; var = sq.x * invN - mu * mu;
        xn[0] = (y.x - mu) * rsqrtf(var + 1e-5f) * g.x + b.x;
        mu = sm.y * invN; var = sq.y * invN - mu * mu;
        xn[1] = (y.y - mu) * rsqrtf(var + 1e-5f) * g.y + b.y;
        mu = sm.z * invN; var = sq.z * invN - mu * mu;
        xn[2] = (y.z - mu) * rsqrtf(var + 1e-5f) * g.z + b.z;
        mu = sm.w * invN; var = sq.w * invN - mu * mu;
        xn[3] = (y.w - mu) * rsqrtf(var + 1e-5f) * g.w + b.w;
    }

    float ss = xn[0] * xn[0] + xn[1] * xn[1] + xn[2] * xn[2] + xn[3] * xn[3];
#pragma unroll
    for (int o = 16; o > 0; o >>= 1)
        ss += __shfl_xor_sync(0xffffffffu, ss, o);

    const float inv = 1.f / (sqrtf(ss) + 1e-6f);
    float4 o4;
    o4.x = xn[0] * inv; o4.y = xn[1] * inv; o4.z = xn[2] * inv; o4.w = xn[3] * inv;
    *(float4*)(Xo + (size_t)w * D + c) = o4;
}

// ---------------------------------------------------------------------------
// Launch
// ---------------------------------------------------------------------------
extern "C" void kernel_launch(void* const* d_in, const int* in_sizes, int n_in,
                              void* d_out, int out_size)
{
    const float* X    = (const float*)d_in[0];
    const int*   n0   = (const int*)  d_in[1];
    const int*   n1   = (const int*)  d_in[2];
    const float* Wa0  = (const float*)d_in[3];
    const float* ba0  = (const float*)d_in[4];
    const float* Wa1  = (const float*)d_in[5];
    const float* ba1  = (const float*)d_in[6];
    const float* W0   = (const float*)d_in[7];
    const float* b0   = (const float*)d_in[8];
    const float* W1   = (const float*)d_in[9];
    const float* b1   = (const float*)d_in[10];
    const float* gmm  = (const float*)d_in[11];
    const float* beta = (const float*)d_in[12];

    const int N = in_sizes[0] / D;
    const int S = in_sizes[1] / N;

    float *A, *B, *C;
    cudaGetSymbolAddress((void**)&A, g_bufA);
    cudaGetSymbolAddress((void**)&B, g_bufB);
    cudaGetSymbolAddress((void**)&C, g_bufC);

    static bool attr_done = false;
    if (!attr_done) {
        cudaFuncSetAttribute(gemm_tf32_kernel<0>, cudaFuncAttributeMaxDynamicSharedMemorySize, SMEM_BYTES);
        cudaFuncSetAttribute(gemm_tf32_kernel<1>, cudaFuncAttributeMaxDynamicSharedMemorySize, SMEM_BYTES);
        cudaFuncSetAttribute(gemm_tf32_kernel<2>, cudaFuncAttributeMaxDynamicSharedMemorySize, SMEM_BYTES);
        attr_done = true;
    }

    const int gemm_blocks = (N + BM - 1) / BM;
    const int warp_blocks = (N + 7) / 8;

    // ---- Layer 0 ----
    // Z0 = relu(X @ Wa0 + ba0); extra block zeroes BN stat accumulators.
    gemm_tf32_kernel<1><<<gemm_blocks + 1, 256, SMEM_BYTES>>>(X, nullptr, Wa0, ba0, A, N, D, 1);
    // agg0 = max_s Z0[neigh0]
    gathermax_kernel<<<warp_blocks, 256>>>(A, n0, B, N, S);
    // Y = relu([X, agg0] @ W0 + b0); epilogue accumulates BN column stats.
    gemm_tf32_kernel<2><<<gemm_blocks, 256, SMEM_BYTES>>>(X, B, W0, b0, C, N, 2 * D, 1);
    // BatchNorm + row L2 normalize -> X1 (in A)
    bn_norm_kernel<<<warp_blocks, 256>>>(C, gmm, beta, A, N, 1.f / (float)N);

    // ---- Layer 1 ----
    // Z1 = relu(X1 @ Wa1 + ba1)
    gemm_tf32_kernel<0><<<gemm_blocks, 256, SMEM_BYTES>>>(A, nullptr, Wa1, ba1, C, N, D, 1);
    // agg1 = max_s Z1[neigh1]
    gathermax_kernel<<<warp_blocks, 256>>>(C, n1, B, N, S);
    // out = [X1, agg1] @ W1 + b1   (no activation)
    gemm_tf32_kernel<0><<<gemm_blocks, 256, SMEM_BYTES>>>(A, B, W1, b1, (float*)d_out, N, 2 * D, 0);
}

// round 7
// speedup vs baseline: 1.9737x; 1.1177x over previous
#include <cuda_runtime.h>
#include <cuda_fp16.h>
#include <cstdint>
#include <cstddef>

#define D 128
#define BM 128        // GEMM rows per block
#define KCH 32        // GEMM K-chunk (4 k8 steps)

// Dynamic smem layout (uint32 units), double buffered:
//   Af stage s: [8 mt][4 kt][32 lane][4]  -> 4096 u32 per stage
//   Bf stage s: [4 kt][16 n8][32 lane][2] -> 4096 u32 per stage
#define AF_STG 4096
#define BF_BASE 8192
#define SMEM_BYTES (16384 * 4)

// Scratch: fp32 ping-pong buffers + BN stat accumulators.
// g_bufC doubles as the fp16 gather table (aliased as __half*).
__device__ __align__(16) float g_bufA[50000 * 128];
__device__ __align__(16) float g_bufB[50000 * 128];
__device__ __align__(16) float g_bufC[50000 * 128];
__device__ float g_sums[D];
__device__ float g_sumsq[D];

__device__ __forceinline__ uint32_t f2tf32(float x) {
    uint32_t u;
    asm("cvt.rna.tf32.f32 %0, %1;" : "=r"(u) : "f"(x));
    return u;
}

__device__ __forceinline__ void mma_tf32(float* c, const uint32_t* a, const uint32_t* b) {
    asm volatile(
        "mma.sync.aligned.m16n8k8.row.col.f32.tf32.tf32.f32 "
        "{%0,%1,%2,%3}, {%4,%5,%6,%7}, {%8,%9}, {%0,%1,%2,%3};"
        : "+f"(c[0]), "+f"(c[1]), "+f"(c[2]), "+f"(c[3])
        : "r"(a[0]), "r"(a[1]), "r"(a[2]), "r"(a[3]), "r"(b[0]), "r"(b[1]));
}

// ---------------------------------------------------------------------------
// C = act( concat(X1, X2)[N,K] @ W[K,128] + bias )   -- TF32 tensor core
// MODE 0: plain.  MODE 1: one extra grid block zeroes BN stat accumulators.
// MODE 2: epilogue also accumulates post-relu column sum/sumsq (atomics).
// OUTH 1: write C as fp16 (gather table).  OUTH 0: write fp32.
// ---------------------------------------------------------------------------
template <int MODE, int OUTH>
__global__ __launch_bounds__(256) void gemm_tf32_kernel(
    const float* __restrict__ X1, const float* __restrict__ X2,
    const float* __restrict__ W, const float* __restrict__ bias,
    void* __restrict__ Cout, int N, int K, int do_relu)
{
    extern __shared__ uint32_t dynsmem[];

    if (MODE == 1 && blockIdx.x == gridDim.x - 1) {
        if (threadIdx.x < D) {
            g_sums[threadIdx.x] = 0.f;
            g_sumsq[threadIdx.x] = 0.f;
        }
        return;
    }

    const int tid  = threadIdx.x;
    const int lane = tid & 31;
    const int wid  = tid >> 5;
    const int wM   = wid >> 2;        // 0..1 -> M offset wM*64
    const int wN   = wid & 3;         // 0..3 -> N offset wN*32
    const int g    = lane >> 2;       // fragment group 0..7
    const int tg   = lane & 3;        // thread-in-group 0..3
    const int m0   = blockIdx.x * BM;

    const int ar  = tid >> 1;              // A: row 0..127, 16 floats each
    const int ab  = (tid & 1) * 16;        // A: col base {0,16}
    const int bk  = tid >> 3;              // B: k row 0..31, 16 floats each
    const int bc4 = (tid & 7) * 16;        // B: col base

    float4 ra[4], rb[4];
    const int nchunk = K / KCH;

    auto load_chunk = [&](int c) {
        const float* src = (c * KCH < D) ? X1 : X2;
        const int    kk  = (c * KCH < D) ? c * KCH : c * KCH - D;
        const int    gr  = m0 + ar;
        if (gr < N) {
#pragma unroll
            for (int h = 0; h < 4; h++)
                ra[h] = *(const float4*)(src + (size_t)gr * D + kk + ab + h * 4);
        } else {
#pragma unroll
            for (int h = 0; h < 4; h++)
                ra[h] = make_float4(0.f, 0.f, 0.f, 0.f);
        }
        const float* wrow = W + (size_t)(c * KCH + bk) * D + bc4;
#pragma unroll
        for (int h = 0; h < 4; h++)
            rb[h] = *(const float4*)(wrow + h * 4);
    };

    auto stage_chunk = [&](int s) {
        uint32_t* Afs = dynsmem + s * AF_STG;
        uint32_t* Bfs = dynsmem + BF_BASE + s * AF_STG;
        const int mt  = ar >> 4;
        const int r16 = ar & 15;
        const int ga  = r16 & 7;
        const int vh  = r16 >> 3;
#pragma unroll
        for (int h = 0; h < 4; h++) {
            const int c4 = ab + h * 4;
            const int kt = c4 >> 3;
            const int ch = (c4 >> 2) & 1;
            const float* v = (const float*)&ra[h];
#pragma unroll
            for (int j = 0; j < 4; j++)
                Afs[(((mt * 4 + kt) * 32) + ga * 4 + j) * 4 + ch * 2 + vh] = f2tf32(v[j]);
        }
        const int kt  = bk >> 3;
        const int k8  = bk & 7;
        const int btg = k8 & 3;
        const int bv  = k8 >> 2;
#pragma unroll
        for (int h = 0; h < 4; h++) {
            const float* v = (const float*)&rb[h];
#pragma unroll
            for (int j = 0; j < 4; j++) {
                const int col = bc4 + h * 4 + j;
                Bfs[(((kt * 16 + (col >> 3)) * 32) + (col & 7) * 4 + btg) * 2 + bv] = f2tf32(v[j]);
            }
        }
    };

    float acc[4][4][4];
#pragma unroll
    for (int mt = 0; mt < 4; mt++)
#pragma unroll
        for (int nt = 0; nt < 4; nt++)
#pragma unroll
            for (int i = 0; i < 4; i++) acc[mt][nt][i] = 0.f;

    load_chunk(0);
    stage_chunk(0);
    __syncthreads();

    for (int c = 0; c < nchunk; c++) {
        const int s = c & 1;
        if (c + 1 < nchunk) load_chunk(c + 1);   // LDG in flight during MMAs

        const uint32_t* Afs = dynsmem + s * AF_STG;
        const uint32_t* Bfs = dynsmem + BF_BASE + s * AF_STG;
#pragma unroll
        for (int kt = 0; kt < 4; kt++) {
            uint32_t a[4][4], b[4][2];
#pragma unroll
            for (int mt = 0; mt < 4; mt++) {
                const uint4 va = *(const uint4*)&Afs[((((wM * 4 + mt) * 4 + kt) * 32) + lane) * 4];
                a[mt][0] = va.x; a[mt][1] = va.y; a[mt][2] = va.z; a[mt][3] = va.w;
            }
#pragma unroll
            for (int nt = 0; nt < 4; nt++) {
                const uint2 vb = *(const uint2*)&Bfs[(((kt * 16 + wN * 4 + nt) * 32) + lane) * 2];
                b[nt][0] = vb.x; b[nt][1] = vb.y;
            }
#pragma unroll
            for (int mt = 0; mt < 4; mt++)
#pragma unroll
                for (int nt = 0; nt < 4; nt++)
                    mma_tf32(acc[mt][nt], a[mt], b[nt]);
        }

        if (c + 1 < nchunk) {
            stage_chunk(s ^ 1);     // STS overlap the in-flight MMAs
            __syncthreads();
        }
    }

    // ---- epilogue: bias (+relu), optional BN stats, write fp32 or fp16 ----
    float* Cf  = (float*)Cout;
    __half* Ch = (__half*)Cout;

    float cs[8], cq[8];
    if (MODE == 2) {
#pragma unroll
        for (int i = 0; i < 8; i++) { cs[i] = 0.f; cq[i] = 0.f; }
    }

#pragma unroll
    for (int nt = 0; nt < 4; nt++) {
        const int colb = wN * 32 + nt * 8 + 2 * tg;
        const float2 bb = *(const float2*)(bias + colb);
#pragma unroll
        for (int mt = 0; mt < 4; mt++) {
            const int row0 = m0 + wM * 64 + mt * 16 + g;
            float2 o0, o1;
            o0.x = acc[mt][nt][0] + bb.x;
            o0.y = acc[mt][nt][1] + bb.y;
            o1.x = acc[mt][nt][2] + bb.x;
            o1.y = acc[mt][nt][3] + bb.y;
            if (do_relu) {
                o0.x = fmaxf(o0.x, 0.f); o0.y = fmaxf(o0.y, 0.f);
                o1.x = fmaxf(o1.x, 0.f); o1.y = fmaxf(o1.y, 0.f);
            }
            const bool v0 = row0 < N, v1 = row0 + 8 < N;
            if (MODE == 2) {
                if (v0) {
                    cs[nt * 2]     += o0.x;  cq[nt * 2]     += o0.x * o0.x;
                    cs[nt * 2 + 1] += o0.y;  cq[nt * 2 + 1] += o0.y * o0.y;
                }
                if (v1) {
                    cs[nt * 2]     += o1.x;  cq[nt * 2]     += o1.x * o1.x;
                    cs[nt * 2 + 1] += o1.y;  cq[nt * 2 + 1] += o1.y * o1.y;
                }
            }
            if (OUTH) {
                if (v0) *(half2*)(Ch + (size_t)row0 * D + colb)       = __floats2half2_rn(o0.x, o0.y);
                if (v1) *(half2*)(Ch + (size_t)(row0 + 8) * D + colb) = __floats2half2_rn(o1.x, o1.y);
            } else {
                if (v0) *(float2*)(Cf + (size_t)row0 * D + colb)       = o0;
                if (v1) *(float2*)(Cf + (size_t)(row0 + 8) * D + colb) = o1;
            }
        }
    }

    if (MODE == 2) {
#pragma unroll
        for (int o = 4; o < 32; o <<= 1) {
#pragma unroll
            for (int i = 0; i < 8; i++) {
                cs[i] += __shfl_xor_sync(0xffffffffu, cs[i], o);
                cq[i] += __shfl_xor_sync(0xffffffffu, cq[i], o);
            }
        }
        if (g == 0) {
#pragma unroll
            for (int i = 0; i < 8; i++) {
                const int col = wN * 32 + (i >> 1) * 8 + 2 * tg + (i & 1);
                atomicAdd(&g_sums[col], cs[i]);
                atomicAdd(&g_sumsq[col], cq[i]);
            }
        }
    }
}

// ---------------------------------------------------------------------------
// A[n,:] = max over s of Zh[neigh[n,s],:]  (fp16 table: 256 B/row)
// Warp per node; lane covers 4 halves (uint2) per neighbor row; __hmax2.
// Output fp32 (exact fp16->fp32 widening).
// ---------------------------------------------------------------------------
__global__ __launch_bounds__(256) void gathermax_h_kernel(
    const __half* __restrict__ Zh, const int* __restrict__ nb,
    float* __restrict__ A, int N, int S)
{
    const int w    = (int)((blockIdx.x * (size_t)blockDim.x + threadIdx.x) >> 5);
    const int lane = threadIdx.x & 31;
    if (w >= N) return;

    int idx = 0;
    if (lane < S) idx = nb[(size_t)w * S + lane];

    const __half ninf = __ushort_as_half(0xFC00);
    half2 m0 = __halves2half2(ninf, ninf);
    half2 m1 = m0;
    const int coff = lane * 4;   // half index within row

    if (S == 25) {
#pragma unroll
        for (int s = 0; s < 25; s++) {
            const int j = __shfl_sync(0xffffffffu, idx, s);
            const uint2 v = *(const uint2*)(Zh + (size_t)j * D + coff);
            m0 = __hmax2(m0, *(const half2*)&v.x);
            m1 = __hmax2(m1, *(const half2*)&v.y);
        }
    } else {
        for (int s = 0; s < S; s++) {
            const int j = __shfl_sync(0xffffffffu, idx, s);
            const uint2 v = *(const uint2*)(Zh + (size_t)j * D + coff);
            m0 = __hmax2(m0, *(const half2*)&v.x);
            m1 = __hmax2(m1, *(const half2*)&v.y);
        }
    }
    const float2 f0 = __half22float2(m0);
    const float2 f1 = __half22float2(m1);
    *(float4*)(A + (size_t)w * D + coff) = make_float4(f0.x, f0.y, f1.x, f1.y);
}

// ---------------------------------------------------------------------------
// BatchNorm (batch stats) + row L2 normalize. Warp per row.
// ---------------------------------------------------------------------------
__global__ __launch_bounds__(256) void bn_norm_kernel(
    const float* __restrict__ Y, const float* __restrict__ gamma,
    const float* __restrict__ beta, float* __restrict__ Xo, int N, float invN)
{
    const int w    = (int)((blockIdx.x * (size_t)blockDim.x + threadIdx.x) >> 5);
    const int lane = threadIdx.x & 31;
    if (w >= N) return;
    const int c = lane * 4;

    const float4 y  = *(const float4*)(Y + (size_t)w * D + c);
    const float4 sm = *(const float4*)(g_sums + c);
    const float4 sq = *(const float4*)(g_sumsq + c);
    const float4 g  = *(const float4*)(gamma + c);
    const float4 b  = *(const float4*)(beta + c);

    float xn[4];
    {
        float mu, var;
        mu = sm.x * invN; var = sq.x * invN - mu * mu;
        xn[0] = (y.x - mu) * rsqrtf(var + 1e-5f) * g.x + b.x;
        mu = sm.y * invN; var = sq.y * invN - mu * mu;
        xn[1] = (y.y - mu) * rsqrtf(var + 1e-5f) * g.y + b.y;
        mu = sm.z * invN; var = sq.z * invN - mu * mu;
        xn[2] = (y.z - mu) * rsqrtf(var + 1e-5f) * g.z + b.z;
        mu = sm.w * invN; var = sq.w * invN - mu * mu;
        xn[3] = (y.w - mu) * rsqrtf(var + 1e-5f) * g.w + b.w;
    }

    float ss = xn[0] * xn[0] + xn[1] * xn[1] + xn[2] * xn[2] + xn[3] * xn[3];
#pragma unroll
    for (int o = 16; o > 0; o >>= 1)
        ss += __shfl_xor_sync(0xffffffffu, ss, o);

    const float inv = 1.f / (sqrtf(ss) + 1e-6f);
    float4 o4;
    o4.x = xn[0] * inv; o4.y = xn[1] * inv; o4.z = xn[2] * inv; o4.w = xn[3] * inv;
    *(float4*)(Xo + (size_t)w * D + c) = o4;
}

// ---------------------------------------------------------------------------
// Launch
// ---------------------------------------------------------------------------
extern "C" void kernel_launch(void* const* d_in, const int* in_sizes, int n_in,
                              void* d_out, int out_size)
{
    const float* X    = (const float*)d_in[0];
    const int*   n0   = (const int*)  d_in[1];
    const int*   n1   = (const int*)  d_in[2];
    const float* Wa0  = (const float*)d_in[3];
    const float* ba0  = (const float*)d_in[4];
    const float* Wa1  = (const float*)d_in[5];
    const float* ba1  = (const float*)d_in[6];
    const float* W0   = (const float*)d_in[7];
    const float* b0   = (const float*)d_in[8];
    const float* W1   = (const float*)d_in[9];
    const float* b1   = (const float*)d_in[10];
    const float* gmm  = (const float*)d_in[11];
    const float* beta = (const float*)d_in[12];

    const int N = in_sizes[0] / D;
    const int S = in_sizes[1] / N;

    float *A, *B, *C;
    cudaGetSymbolAddress((void**)&A, g_bufA);
    cudaGetSymbolAddress((void**)&B, g_bufB);
    cudaGetSymbolAddress((void**)&C, g_bufC);
    __half* Zh = (__half*)C;   // fp16 gather table aliases g_bufC

    static bool attr_done = false;
    if (!attr_done) {
        cudaFuncSetAttribute(gemm_tf32_kernel<1, 1>, cudaFuncAttributeMaxDynamicSharedMemorySize, SMEM_BYTES);
        cudaFuncSetAttribute(gemm_tf32_kernel<2, 0>, cudaFuncAttributeMaxDynamicSharedMemorySize, SMEM_BYTES);
        cudaFuncSetAttribute(gemm_tf32_kernel<0, 1>, cudaFuncAttributeMaxDynamicSharedMemorySize, SMEM_BYTES);
        cudaFuncSetAttribute(gemm_tf32_kernel<0, 0>, cudaFuncAttributeMaxDynamicSharedMemorySize, SMEM_BYTES);
        attr_done = true;
    }

    const int gemm_blocks = (N + BM - 1) / BM;
    const int warp_blocks = (N + 7) / 8;

    // ---- Layer 0 ----
    // Z0h = relu(X @ Wa0 + ba0) in fp16; extra block zeroes BN accumulators.
    gemm_tf32_kernel<1, 1><<<gemm_blocks + 1, 256, SMEM_BYTES>>>(X, nullptr, Wa0, ba0, Zh, N, D, 1);
    // agg0 = max_s Z0h[neigh0]  (256 B/row gather)
    gathermax_h_kernel<<<warp_blocks, 256>>>(Zh, n0, B, N, S);
    // Y = relu([X, agg0] @ W0 + b0); epilogue accumulates BN column stats.
    gemm_tf32_kernel<2, 0><<<gemm_blocks, 256, SMEM_BYTES>>>(X, B, W0, b0, C, N, 2 * D, 1);
    // BatchNorm + row L2 normalize -> X1 (in A)
    bn_norm_kernel<<<warp_blocks, 256>>>(C, gmm, beta, A, N, 1.f / (float)N);

    // ---- Layer 1 ----
    // Z1h = relu(X1 @ Wa1 + ba1) in fp16 (overwrites Y; bn_norm already done)
    gemm_tf32_kernel<0, 1><<<gemm_blocks, 256, SMEM_BYTES>>>(A, nullptr, Wa1, ba1, Zh, N, D, 1);
    // agg1 = max_s Z1h[neigh1]
    gathermax_h_kernel<<<warp_blocks, 256>>>(Zh, n1, B, N, S);
    // out = [X1, agg1] @ W1 + b1   (no activation)
    gemm_tf32_kernel<0, 0><<<gemm_blocks, 256, SMEM_BYTES>>>(A, B, W1, b1, (float*)d_out, N, 2 * D, 0);
}

// round 8
// speedup vs baseline: 2.2649x; 1.1476x over previous
#include <cuda_runtime.h>
#include <cuda_fp16.h>
#include <cstdint>
#include <cstddef>

#define D 128
#define BM 128        // GEMM rows per block
#define KCH 32        // GEMM K-chunk (2 k16 steps)

// Dynamic smem (uint32 units), double buffered fp16 fragments:
//   Af stage s: [8 mt][2 kt][32 lane][4] -> 2048 u32 per stage
//   Bf stage s: [2 kt][16 n8][32 lane][2] -> 2048 u32 per stage
#define AF_STG 2048
#define BF_BASE 4096
#define SMEM_BYTES (8192 * 4)

// Scratch: fp32 ping-pong buffers + BN stat accumulators.
// g_bufC doubles as the fp16 gather table (aliased as __half*).
__device__ __align__(16) float g_bufA[50000 * 128];
__device__ __align__(16) float g_bufB[50000 * 128];
__device__ __align__(16) float g_bufC[50000 * 128];
__device__ float g_sums[D];
__device__ float g_sumsq[D];

__device__ __forceinline__ uint32_t pack_h2(float x, float y) {
    half2 h = __floats2half2_rn(x, y);
    return *reinterpret_cast<uint32_t*>(&h);
}

__device__ __forceinline__ void mma_f16(float* c, const uint32_t* a, const uint32_t* b) {
    asm volatile(
        "mma.sync.aligned.m16n8k16.row.col.f32.f16.f16.f32 "
        "{%0,%1,%2,%3}, {%4,%5,%6,%7}, {%8,%9}, {%0,%1,%2,%3};"
        : "+f"(c[0]), "+f"(c[1]), "+f"(c[2]), "+f"(c[3])
        : "r"(a[0]), "r"(a[1]), "r"(a[2]), "r"(a[3]), "r"(b[0]), "r"(b[1]));
}

// ---------------------------------------------------------------------------
// C = act( concat(X1, X2)[N,K] @ W[K,128] + bias )   -- FP16 tensor core
// MODE 0: plain.  MODE 1: one extra grid block zeroes BN stat accumulators.
// MODE 2: epilogue also accumulates post-relu column sum/sumsq (atomics).
// OUTH 1: write C as fp16 (gather table).  OUTH 0: write fp32.
//
// 128x128 block tile, 8 warps (2M x 4N), warp tile 64x32 (4x4 m16n8k16),
// K in 32-chunks (2 k16 steps), double-buffered fragment-major fp16 smem.
// ---------------------------------------------------------------------------
template <int MODE, int OUTH>
__global__ __launch_bounds__(256) void gemm_f16_kernel(
    const float* __restrict__ X1, const float* __restrict__ X2,
    const float* __restrict__ W, const float* __restrict__ bias,
    void* __restrict__ Cout, int N, int K, int do_relu)
{
    extern __shared__ uint32_t dynsmem[];

    if (MODE == 1 && blockIdx.x == gridDim.x - 1) {
        if (threadIdx.x < D) {
            g_sums[threadIdx.x] = 0.f;
            g_sumsq[threadIdx.x] = 0.f;
        }
        return;
    }

    const int tid  = threadIdx.x;
    const int lane = tid & 31;
    const int wid  = tid >> 5;
    const int wM   = wid >> 2;        // 0..1 -> M offset wM*64
    const int wN   = wid & 3;         // 0..3 -> N offset wN*32
    const int g    = lane >> 2;       // fragment group 0..7
    const int tg   = lane & 3;        // thread-in-group 0..3
    const int m0   = blockIdx.x * BM;

    // A staging: thread covers row ar, cols ab..ab+15 (one full k16 tile).
    const int ar = tid >> 1;               // 0..127
    const int ab = (tid & 1) * 16;         // {0,16} -> kt = ab>>4
    // B staging: thread covers k rows 2p,2p+1, cols cb..cb+7 (one n8 tile).
    const int p  = tid & 15;               // k-row pair 0..15
    const int cb = (tid >> 4) * 8;         // col base 0..120

    float4 ra[4];        // A row: 16 floats
    float4 rb0[2], rb1[2]; // B rows 2p / 2p+1: 8 floats each
    const int nchunk = K / KCH;

    auto load_chunk = [&](int c) {
        const float* src = (c * KCH < D) ? X1 : X2;
        const int    kk  = (c * KCH < D) ? c * KCH : c * KCH - D;
        const int    gr  = m0 + ar;
        if (gr < N) {
#pragma unroll
            for (int h = 0; h < 4; h++)
                ra[h] = *(const float4*)(src + (size_t)gr * D + kk + ab + h * 4);
        } else {
#pragma unroll
            for (int h = 0; h < 4; h++)
                ra[h] = make_float4(0.f, 0.f, 0.f, 0.f);
        }
        const float* w0 = W + (size_t)(c * KCH + 2 * p) * D + cb;
        const float* w1 = w0 + D;
        rb0[0] = *(const float4*)(w0);
        rb0[1] = *(const float4*)(w0 + 4);
        rb1[0] = *(const float4*)(w1);
        rb1[1] = *(const float4*)(w1 + 4);
    };

    auto stage_chunk = [&](int s) {
        uint32_t* Afs = dynsmem + s * AF_STG;
        uint32_t* Bfs = dynsmem + BF_BASE + s * AF_STG;

        // --- A: fragment element (ar, ab+kk) -> lane ga*4+tg, reg ---
        const int mt  = ar >> 4;
        const int r16 = ar & 15;
        const int ga  = r16 & 7;
        const int vh  = r16 >> 3;          // 0 -> regs {0,2}, 1 -> regs {1,3}
        const int kt  = ab >> 4;
        const float* av = (const float*)ra;
#pragma unroll
        for (int t = 0; t < 8; t++) {      // half2 over cols 2t, 2t+1
            const int ln  = ga * 4 + (t & 3);
            const int reg = (t >> 2) * 2 + vh;
            Afs[(((mt * 2 + kt) * 32) + ln) * 4 + reg] = pack_h2(av[2 * t], av[2 * t + 1]);
        }

        // --- B: element (2p+dk, cb+j) -> lane j'*4+tg, reg ---
        const int bkt = p >> 3;
        const int btg = p & 3;
        const int brg = (p >> 2) & 1;
        const int n8  = tid >> 4;
        const float* b0v = (const float*)rb0;
        const float* b1v = (const float*)rb1;
#pragma unroll
        for (int j = 0; j < 8; j++) {
            const int ln = j * 4 + btg;
            Bfs[(((bkt * 16 + n8) * 32) + ln) * 2 + brg] = pack_h2(b0v[j], b1v[j]);
        }
    };

    float acc[4][4][4];
#pragma unroll
    for (int mt = 0; mt < 4; mt++)
#pragma unroll
        for (int nt = 0; nt < 4; nt++)
#pragma unroll
            for (int i = 0; i < 4; i++) acc[mt][nt][i] = 0.f;

    load_chunk(0);
    stage_chunk(0);
    __syncthreads();

    for (int c = 0; c < nchunk; c++) {
        const int s = c & 1;
        if (c + 1 < nchunk) load_chunk(c + 1);   // LDG in flight during MMAs

        const uint32_t* Afs = dynsmem + s * AF_STG;
        const uint32_t* Bfs = dynsmem + BF_BASE + s * AF_STG;
#pragma unroll
        for (int kt = 0; kt < 2; kt++) {
            uint32_t a[4][4], b[4][2];
#pragma unroll
            for (int mt = 0; mt < 4; mt++) {
                const uint4 va = *(const uint4*)&Afs[((((wM * 4 + mt) * 2 + kt) * 32) + lane) * 4];
                a[mt][0] = va.x; a[mt][1] = va.y; a[mt][2] = va.z; a[mt][3] = va.w;
            }
#pragma unroll
            for (int nt = 0; nt < 4; nt++) {
                const uint2 vb = *(const uint2*)&Bfs[(((kt * 16 + wN * 4 + nt) * 32) + lane) * 2];
                b[nt][0] = vb.x; b[nt][1] = vb.y;
            }
#pragma unroll
            for (int mt = 0; mt < 4; mt++)
#pragma unroll
                for (int nt = 0; nt < 4; nt++)
                    mma_f16(acc[mt][nt], a[mt], b[nt]);
        }

        if (c + 1 < nchunk) {
            stage_chunk(s ^ 1);     // STS overlap the in-flight MMAs
            __syncthreads();
        }
    }

    // ---- epilogue: bias (+relu), optional BN stats, write fp32 or fp16 ----
    float* Cf  = (float*)Cout;
    __half* Ch = (__half*)Cout;

    float cs[8], cq[8];
    if (MODE == 2) {
#pragma unroll
        for (int i = 0; i < 8; i++) { cs[i] = 0.f; cq[i] = 0.f; }
    }

#pragma unroll
    for (int nt = 0; nt < 4; nt++) {
        const int colb = wN * 32 + nt * 8 + 2 * tg;
        const float2 bb = *(const float2*)(bias + colb);
#pragma unroll
        for (int mt = 0; mt < 4; mt++) {
            const int row0 = m0 + wM * 64 + mt * 16 + g;
            float2 o0, o1;
            o0.x = acc[mt][nt][0] + bb.x;
            o0.y = acc[mt][nt][1] + bb.y;
            o1.x = acc[mt][nt][2] + bb.x;
            o1.y = acc[mt][nt][3] + bb.y;
            if (do_relu) {
                o0.x = fmaxf(o0.x, 0.f); o0.y = fmaxf(o0.y, 0.f);
                o1.x = fmaxf(o1.x, 0.f); o1.y = fmaxf(o1.y, 0.f);
            }
            const bool v0 = row0 < N, v1 = row0 + 8 < N;
            if (MODE == 2) {
                if (v0) {
                    cs[nt * 2]     += o0.x;  cq[nt * 2]     += o0.x * o0.x;
                    cs[nt * 2 + 1] += o0.y;  cq[nt * 2 + 1] += o0.y * o0.y;
                }
                if (v1) {
                    cs[nt * 2]     += o1.x;  cq[nt * 2]     += o1.x * o1.x;
                    cs[nt * 2 + 1] += o1.y;  cq[nt * 2 + 1] += o1.y * o1.y;
                }
            }
            if (OUTH) {
                if (v0) *(uint32_t*)(Ch + (size_t)row0 * D + colb)       = pack_h2(o0.x, o0.y);
                if (v1) *(uint32_t*)(Ch + (size_t)(row0 + 8) * D + colb) = pack_h2(o1.x, o1.y);
            } else {
                if (v0) *(float2*)(Cf + (size_t)row0 * D + colb)       = o0;
                if (v1) *(float2*)(Cf + (size_t)(row0 + 8) * D + colb) = o1;
            }
        }
    }

    if (MODE == 2) {
#pragma unroll
        for (int o = 4; o < 32; o <<= 1) {
#pragma unroll
            for (int i = 0; i < 8; i++) {
                cs[i] += __shfl_xor_sync(0xffffffffu, cs[i], o);
                cq[i] += __shfl_xor_sync(0xffffffffu, cq[i], o);
            }
        }
        if (g == 0) {
#pragma unroll
            for (int i = 0; i < 8; i++) {
                const int col = wN * 32 + (i >> 1) * 8 + 2 * tg + (i & 1);
                atomicAdd(&g_sums[col], cs[i]);
                atomicAdd(&g_sumsq[col], cq[i]);
            }
        }
    }
}

// ---------------------------------------------------------------------------
// A[n,:] = max over s of Zh[neigh[n,s],:]  (fp16 table: 256 B/row)
// HALF-WARP per node: 16 lanes x uint4 (8 halves) per neighbor row.
// ---------------------------------------------------------------------------
__global__ __launch_bounds__(256) void gathermax_h_kernel(
    const __half* __restrict__ Zh, const int* __restrict__ nb,
    float* __restrict__ A, int N, int S)
{
    const int warp = (int)((blockIdx.x * (size_t)blockDim.x + threadIdx.x) >> 5);
    const int lane = threadIdx.x & 31;
    const int sub  = lane >> 4;           // half-warp 0/1
    const int li   = lane & 15;           // lane within half-warp
    const int node = warp * 2 + sub;
    if (node >= N) return;

    // Indices: li covers s=li and s=li+16 (guarded).
    int idx0 = nb[(size_t)node * S + (li < S ? li : 0)];
    int idx1 = (li + 16 < S) ? nb[(size_t)node * S + li + 16] : 0;

    const __half ninf = __ushort_as_half(0xFC00);
    half2 m0 = __halves2half2(ninf, ninf);
    half2 m1 = m0, m2 = m0, m3 = m0;
    const int coff = li * 8;              // half index within row

    for (int s = 0; s < S; s++) {
        const int src = sub * 16 + (s < 16 ? s : s - 16);
        const int j = __shfl_sync(0xffffffffu, s < 16 ? idx0 : idx1, src);
        const uint4 v = *(const uint4*)(Zh + (size_t)j * D + coff);
        m0 = __hmax2(m0, *(const half2*)&v.x);
        m1 = __hmax2(m1, *(const half2*)&v.y);
        m2 = __hmax2(m2, *(const half2*)&v.z);
        m3 = __hmax2(m3, *(const half2*)&v.w);
    }
    const float2 f0 = __half22float2(m0);
    const float2 f1 = __half22float2(m1);
    const float2 f2 = __half22float2(m2);
    const float2 f3 = __half22float2(m3);
    *(float4*)(A + (size_t)node * D + coff)     = make_float4(f0.x, f0.y, f1.x, f1.y);
    *(float4*)(A + (size_t)node * D + coff + 4) = make_float4(f2.x, f2.y, f3.x, f3.y);
}

// ---------------------------------------------------------------------------
// BatchNorm (batch stats) + row L2 normalize. Warp per row.
// ---------------------------------------------------------------------------
__global__ __launch_bounds__(256) void bn_norm_kernel(
    const float* __restrict__ Y, const float* __restrict__ gamma,
    const float* __restrict__ beta, float* __restrict__ Xo, int N, float invN)
{
    const int w    = (int)((blockIdx.x * (size_t)blockDim.x + threadIdx.x) >> 5);
    const int lane = threadIdx.x & 31;
    if (w >= N) return;
    const int c = lane * 4;

    const float4 y  = *(const float4*)(Y + (size_t)w * D + c);
    const float4 sm = *(const float4*)(g_sums + c);
    const float4 sq = *(const float4*)(g_sumsq + c);
    const float4 g  = *(const float4*)(gamma + c);
    const float4 b  = *(const float4*)(beta + c);

    float xn[4];
    {
        float mu, var;
        mu = sm.x * invN; var = sq.x * invN - mu * mu;
        xn[0] = (y.x - mu) * rsqrtf(var + 1e-5f) * g.x + b.x;
        mu = sm.y * invN; var = sq.y * invN - mu * mu;
        xn[1] = (y.y - mu) * rsqrtf(var + 1e-5f) * g.y + b.y;
        mu = sm.z * invN; var = sq.z * invN - mu * mu;
        xn[2] = (y.z - mu) * rsqrtf(var + 1e-5f) * g.z + b.z;
        mu = sm.w * invN; var = sq.w * invN - mu * mu;
        xn[3] = (y.w - mu) * rsqrtf(var + 1e-5f) * g.w + b.w;
    }

    float ss = xn[0] * xn[0] + xn[1] * xn[1] + xn[2] * xn[2] + xn[3] * xn[3];
#pragma unroll
    for (int o = 16; o > 0; o >>= 1)
        ss += __shfl_xor_sync(0xffffffffu, ss, o);

    const float inv = 1.f / (sqrtf(ss) + 1e-6f);
    float4 o4;
    o4.x = xn[0] * inv; o4.y = xn[1] * inv; o4.z = xn[2] * inv; o4.w = xn[3] * inv;
    *(float4*)(Xo + (size_t)w * D + c) = o4;
}

// ---------------------------------------------------------------------------
// Launch
// ---------------------------------------------------------------------------
extern "C" void kernel_launch(void* const* d_in, const int* in_sizes, int n_in,
                              void* d_out, int out_size)
{
    const float* X    = (const float*)d_in[0];
    const int*   n0   = (const int*)  d_in[1];
    const int*   n1   = (const int*)  d_in[2];
    const float* Wa0  = (const float*)d_in[3];
    const float* ba0  = (const float*)d_in[4];
    const float* Wa1  = (const float*)d_in[5];
    const float* ba1  = (const float*)d_in[6];
    const float* W0   = (const float*)d_in[7];
    const float* b0   = (const float*)d_in[8];
    const float* W1   = (const float*)d_in[9];
    const float* b1   = (const float*)d_in[10];
    const float* gmm  = (const float*)d_in[11];
    const float* beta = (const float*)d_in[12];

    const int N = in_sizes[0] / D;
    const int S = in_sizes[1] / N;

    float *A, *B, *C;
    cudaGetSymbolAddress((void**)&A, g_bufA);
    cudaGetSymbolAddress((void**)&B, g_bufB);
    cudaGetSymbolAddress((void**)&C, g_bufC);
    __half* Zh = (__half*)C;   // fp16 gather table aliases g_bufC

    const int gemm_blocks   = (N + BM - 1) / BM;
    const int warp_blocks   = (N + 7) / 8;     // bn_norm: warp per row
    const int gather_blocks = (N + 15) / 16;   // gather: half-warp per node

    // ---- Layer 0 ----
    // Z0h = relu(X @ Wa0 + ba0) in fp16; extra block zeroes BN accumulators.
    gemm_f16_kernel<1, 1><<<gemm_blocks + 1, 256, SMEM_BYTES>>>(X, nullptr, Wa0, ba0, Zh, N, D, 1);
    // agg0 = max_s Z0h[neigh0]
    gathermax_h_kernel<<<gather_blocks, 256>>>(Zh, n0, B, N, S);
    // Y = relu([X, agg0] @ W0 + b0); epilogue accumulates BN column stats.
    gemm_f16_kernel<2, 0><<<gemm_blocks, 256, SMEM_BYTES>>>(X, B, W0, b0, C, N, 2 * D, 1);
    // BatchNorm + row L2 normalize -> X1 (in A)
    bn_norm_kernel<<<warp_blocks, 256>>>(C, gmm, beta, A, N, 1.f / (float)N);

    // ---- Layer 1 ----
    // Z1h = relu(X1 @ Wa1 + ba1) in fp16 (overwrites Y; bn_norm already done)
    gemm_f16_kernel<0, 1><<<gemm_blocks, 256, SMEM_BYTES>>>(A, nullptr, Wa1, ba1, Zh, N, D, 1);
    // agg1 = max_s Z1h[neigh1]
    gathermax_h_kernel<<<gather_blocks, 256>>>(Zh, n1, B, N, S);
    // out = [X1, agg1] @ W1 + b1   (no activation)
    gemm_f16_kernel<0, 0><<<gemm_blocks, 256, SMEM_BYTES>>>(A, B, W1, b1, (float*)d_out, N, 2 * D, 0);
}

// round 10
// speedup vs baseline: 2.2659x; 1.0004x over previous
#include <cuda_runtime.h>
#include <cuda_fp16.h>
#include <cstdint>
#include <cstddef>

#define D 128
#define BM 128        // GEMM rows per block
#define KCH 32        // GEMM K-chunk (2 k16 steps)

// Dynamic smem (uint32 units), double buffered fp16 fragments:
//   Af stage s: [8 mt][2 kt][32 lane][4] -> 2048 u32 per stage
//   Bf stage s: [2 kt][16 n8][32 lane][2] -> 2048 u32 per stage
#define AF_STG 2048
#define BF_BASE 4096
#define SMEM_BYTES (8192 * 4)

// Scratch: fp32 ping-pong buffers + BN stat accumulators.
// g_bufC doubles as the fp16 gather table (aliased as __half*).
__device__ __align__(16) float g_bufA[50000 * 128];
__device__ __align__(16) float g_bufB[50000 * 128];
__device__ __align__(16) float g_bufC[50000 * 128];
__device__ float g_sums[D];
__device__ float g_sumsq[D];

__device__ __forceinline__ uint32_t pack_h2(float x, float y) {
    half2 h = __floats2half2_rn(x, y);
    return *reinterpret_cast<uint32_t*>(&h);
}

__device__ __forceinline__ void mma_f16(float* c, const uint32_t* a, const uint32_t* b) {
    asm volatile(
        "mma.sync.aligned.m16n8k16.row.col.f32.f16.f16.f32 "
        "{%0,%1,%2,%3}, {%4,%5,%6,%7}, {%8,%9}, {%0,%1,%2,%3};"
        : "+f"(c[0]), "+f"(c[1]), "+f"(c[2]), "+f"(c[3])
        : "r"(a[0]), "r"(a[1]), "r"(a[2]), "r"(a[3]), "r"(b[0]), "r"(b[1]));
}

// ---------------------------------------------------------------------------
// C = act( concat(X1, X2)[N,K] @ W[K,128] + bias )   -- FP16 tensor core
// MODE 0: plain.  MODE 1: one extra grid block zeroes BN stat accumulators.
// MODE 2: epilogue also accumulates post-relu column sum/sumsq (atomics).
// OUTH 1: write C as fp16 (gather table).  OUTH 0: write fp32.
//
// 128x128 block tile, 8 warps (2M x 4N), warp tile 64x32 (4x4 m16n8k16),
// K in 32-chunks (2 k16 steps), double-buffered fragment-major fp16 smem.
// ---------------------------------------------------------------------------
template <int MODE, int OUTH>
__global__ __launch_bounds__(256) void gemm_f16_kernel(
    const float* __restrict__ X1, const float* __restrict__ X2,
    const float* __restrict__ W, const float* __restrict__ bias,
    void* __restrict__ Cout, int N, int K, int do_relu)
{
    extern __shared__ uint32_t dynsmem[];

    if (MODE == 1 && blockIdx.x == gridDim.x - 1) {
        if (threadIdx.x < D) {
            g_sums[threadIdx.x] = 0.f;
            g_sumsq[threadIdx.x] = 0.f;
        }
        return;
    }

    const int tid  = threadIdx.x;
    const int lane = tid & 31;
    const int wid  = tid >> 5;
    const int wM   = wid >> 2;        // 0..1 -> M offset wM*64
    const int wN   = wid & 3;         // 0..3 -> N offset wN*32
    const int g    = lane >> 2;       // fragment group 0..7
    const int tg   = lane & 3;        // thread-in-group 0..3
    const int m0   = blockIdx.x * BM;

    // A staging: thread covers row ar, cols ab..ab+15 (one full k16 tile).
    const int ar = tid >> 1;               // 0..127
    const int ab = (tid & 1) * 16;         // {0,16} -> kt = ab>>4
    // B staging: thread covers k rows 2p,2p+1, cols cb..cb+7 (one n8 tile).
    const int p  = tid & 15;               // k-row pair 0..15
    const int cb = (tid >> 4) * 8;         // col base 0..120

    float4 ra[4];        // A row: 16 floats
    float4 rb0[2], rb1[2]; // B rows 2p / 2p+1: 8 floats each
    const int nchunk = K / KCH;

    auto load_chunk = [&](int c) {
        const float* src = (c * KCH < D) ? X1 : X2;
        const int    kk  = (c * KCH < D) ? c * KCH : c * KCH - D;
        const int    gr  = m0 + ar;
        if (gr < N) {
#pragma unroll
            for (int h = 0; h < 4; h++)
                ra[h] = *(const float4*)(src + (size_t)gr * D + kk + ab + h * 4);
        } else {
#pragma unroll
            for (int h = 0; h < 4; h++)
                ra[h] = make_float4(0.f, 0.f, 0.f, 0.f);
        }
        const float* w0 = W + (size_t)(c * KCH + 2 * p) * D + cb;
        const float* w1 = w0 + D;
        rb0[0] = *(const float4*)(w0);
        rb0[1] = *(const float4*)(w0 + 4);
        rb1[0] = *(const float4*)(w1);
        rb1[1] = *(const float4*)(w1 + 4);
    };

    auto stage_chunk = [&](int s) {
        uint32_t* Afs = dynsmem + s * AF_STG;
        uint32_t* Bfs = dynsmem + BF_BASE + s * AF_STG;

        // --- A: fragment element (ar, ab+kk) -> lane ga*4+tg, reg ---
        const int mt  = ar >> 4;
        const int r16 = ar & 15;
        const int ga  = r16 & 7;
        const int vh  = r16 >> 3;          // 0 -> regs {0,2}, 1 -> regs {1,3}
        const int kt  = ab >> 4;
        const float* av = (const float*)ra;
#pragma unroll
        for (int t = 0; t < 8; t++) {      // half2 over cols 2t, 2t+1
            const int ln  = ga * 4 + (t & 3);
            const int reg = (t >> 2) * 2 + vh;
            Afs[(((mt * 2 + kt) * 32) + ln) * 4 + reg] = pack_h2(av[2 * t], av[2 * t + 1]);
        }

        // --- B: element (2p+dk, cb+j) -> lane j'*4+tg, reg ---
        const int bkt = p >> 3;
        const int btg = p & 3;
        const int brg = (p >> 2) & 1;
        const int n8  = tid >> 4;
        const float* b0v = (const float*)rb0;
        const float* b1v = (const float*)rb1;
#pragma unroll
        for (int j = 0; j < 8; j++) {
            const int ln = j * 4 + btg;
            Bfs[(((bkt * 16 + n8) * 32) + ln) * 2 + brg] = pack_h2(b0v[j], b1v[j]);
        }
    };

    float acc[4][4][4];
#pragma unroll
    for (int mt = 0; mt < 4; mt++)
#pragma unroll
        for (int nt = 0; nt < 4; nt++)
#pragma unroll
            for (int i = 0; i < 4; i++) acc[mt][nt][i] = 0.f;

    load_chunk(0);
    stage_chunk(0);
    __syncthreads();

    for (int c = 0; c < nchunk; c++) {
        const int s = c & 1;
        if (c + 1 < nchunk) load_chunk(c + 1);   // LDG in flight during MMAs

        const uint32_t* Afs = dynsmem + s * AF_STG;
        const uint32_t* Bfs = dynsmem + BF_BASE + s * AF_STG;
#pragma unroll
        for (int kt = 0; kt < 2; kt++) {
            uint32_t a[4][4], b[4][2];
#pragma unroll
            for (int mt = 0; mt < 4; mt++) {
                const uint4 va = *(const uint4*)&Afs[((((wM * 4 + mt) * 2 + kt) * 32) + lane) * 4];
                a[mt][0] = va.x; a[mt][1] = va.y; a[mt][2] = va.z; a[mt][3] = va.w;
            }
#pragma unroll
            for (int nt = 0; nt < 4; nt++) {
                const uint2 vb = *(const uint2*)&Bfs[(((kt * 16 + wN * 4 + nt) * 32) + lane) * 2];
                b[nt][0] = vb.x; b[nt][1] = vb.y;
            }
#pragma unroll
            for (int mt = 0; mt < 4; mt++)
#pragma unroll
                for (int nt = 0; nt < 4; nt++)
                    mma_f16(acc[mt][nt], a[mt], b[nt]);
        }

        if (c + 1 < nchunk) {
            stage_chunk(s ^ 1);     // STS overlap the in-flight MMAs
            __syncthreads();
        }
    }

    // ---- epilogue: bias (+relu), optional BN stats, write fp32 or fp16 ----
    float* Cf  = (float*)Cout;
    __half* Ch = (__half*)Cout;

    float cs[8], cq[8];
    if (MODE == 2) {
#pragma unroll
        for (int i = 0; i < 8; i++) { cs[i] = 0.f; cq[i] = 0.f; }
    }

#pragma unroll
    for (int nt = 0; nt < 4; nt++) {
        const int colb = wN * 32 + nt * 8 + 2 * tg;
        const float2 bb = *(const float2*)(bias + colb);
#pragma unroll
        for (int mt = 0; mt < 4; mt++) {
            const int row0 = m0 + wM * 64 + mt * 16 + g;
            float2 o0, o1;
            o0.x = acc[mt][nt][0] + bb.x;
            o0.y = acc[mt][nt][1] + bb.y;
            o1.x = acc[mt][nt][2] + bb.x;
            o1.y = acc[mt][nt][3] + bb.y;
            if (do_relu) {
                o0.x = fmaxf(o0.x, 0.f); o0.y = fmaxf(o0.y, 0.f);
                o1.x = fmaxf(o1.x, 0.f); o1.y = fmaxf(o1.y, 0.f);
            }
            const bool v0 = row0 < N, v1 = row0 + 8 < N;
            if (MODE == 2) {
                if (v0) {
                    cs[nt * 2]     += o0.x;  cq[nt * 2]     += o0.x * o0.x;
                    cs[nt * 2 + 1] += o0.y;  cq[nt * 2 + 1] += o0.y * o0.y;
                }
                if (v1) {
                    cs[nt * 2]     += o1.x;  cq[nt * 2]     += o1.x * o1.x;
                    cs[nt * 2 + 1] += o1.y;  cq[nt * 2 + 1] += o1.y * o1.y;
                }
            }
            if (OUTH) {
                if (v0) *(uint32_t*)(Ch + (size_t)row0 * D + colb)       = pack_h2(o0.x, o0.y);
                if (v1) *(uint32_t*)(Ch + (size_t)(row0 + 8) * D + colb) = pack_h2(o1.x, o1.y);
            } else {
                if (v0) *(float2*)(Cf + (size_t)row0 * D + colb)       = o0;
                if (v1) *(float2*)(Cf + (size_t)(row0 + 8) * D + colb) = o1;
            }
        }
    }

    if (MODE == 2) {
#pragma unroll
        for (int o = 4; o < 32; o <<= 1) {
#pragma unroll
            for (int i = 0; i < 8; i++) {
                cs[i] += __shfl_xor_sync(0xffffffffu, cs[i], o);
                cq[i] += __shfl_xor_sync(0xffffffffu, cq[i], o);
            }
        }
        if (g == 0) {
#pragma unroll
            for (int i = 0; i < 8; i++) {
                const int col = wN * 32 + (i >> 1) * 8 + 2 * tg + (i & 1);
                atomicAdd(&g_sums[col], cs[i]);
                atomicAdd(&g_sumsq[col], cq[i]);
            }
        }
    }
}

// ---------------------------------------------------------------------------
// A[n,:] = max over s of Zh[neigh[n,s],:]  (fp16 table: 256 B/row)
// HALF-WARP per node: 16 lanes x uint4 (8 halves) per neighbor row.
// ---------------------------------------------------------------------------
__global__ __launch_bounds__(256) void gathermax_h_kernel(
    const __half* __restrict__ Zh, const int* __restrict__ nb,
    float* __restrict__ A, int N, int S)
{
    const int warp = (int)((blockIdx.x * (size_t)blockDim.x + threadIdx.x) >> 5);
    const int lane = threadIdx.x & 31;
    const int sub  = lane >> 4;           // half-warp 0/1
    const int li   = lane & 15;           // lane within half-warp
    const int node = warp * 2 + sub;
    if (node >= N) return;

    // Indices: li covers s=li and s=li+16 (guarded).
    int idx0 = nb[(size_t)node * S + (li < S ? li : 0)];
    int idx1 = (li + 16 < S) ? nb[(size_t)node * S + li + 16] : 0;

    const __half ninf = __ushort_as_half(0xFC00);
    half2 m0 = __halves2half2(ninf, ninf);
    half2 m1 = m0, m2 = m0, m3 = m0;
    const int coff = li * 8;              // half index within row

    for (int s = 0; s < S; s++) {
        const int src = sub * 16 + (s < 16 ? s : s - 16);
        const int j = __shfl_sync(0xffffffffu, s < 16 ? idx0 : idx1, src);
        const uint4 v = *(const uint4*)(Zh + (size_t)j * D + coff);
        m0 = __hmax2(m0, *(const half2*)&v.x);
        m1 = __hmax2(m1, *(const half2*)&v.y);
        m2 = __hmax2(m2, *(const half2*)&v.z);
        m3 = __hmax2(m3, *(const half2*)&v.w);
    }
    const float2 f0 = __half22float2(m0);
    const float2 f1 = __half22float2(m1);
    const float2 f2 = __half22float2(m2);
    const float2 f3 = __half22float2(m3);
    *(float4*)(A + (size_t)node * D + coff)     = make_float4(f0.x, f0.y, f1.x, f1.y);
    *(float4*)(A + (size_t)node * D + coff + 4) = make_float4(f2.x, f2.y, f3.x, f3.y);
}

// ---------------------------------------------------------------------------
// BatchNorm (batch stats) + row L2 normalize. Warp per row.
// ---------------------------------------------------------------------------
__global__ __launch_bounds__(256) void bn_norm_kernel(
    const float* __restrict__ Y, const float* __restrict__ gamma,
    const float* __restrict__ beta, float* __restrict__ Xo, int N, float invN)
{
    const int w    = (int)((blockIdx.x * (size_t)blockDim.x + threadIdx.x) >> 5);
    const int lane = threadIdx.x & 31;
    if (w >= N) return;
    const int c = lane * 4;

    const float4 y  = *(const float4*)(Y + (size_t)w * D + c);
    const float4 sm = *(const float4*)(g_sums + c);
    const float4 sq = *(const float4*)(g_sumsq + c);
    const float4 g  = *(const float4*)(gamma + c);
    const float4 b  = *(const float4*)(beta + c);

    float xn[4];
    {
        float mu, var;
        mu = sm.x * invN; var = sq.x * invN - mu * mu;
        xn[0] = (y.x - mu) * rsqrtf(var + 1e-5f) * g.x + b.x;
        mu = sm.y * invN; var = sq.y * invN - mu * mu;
        xn[1] = (y.y - mu) * rsqrtf(var + 1e-5f) * g.y + b.y;
        mu = sm.z * invN; var = sq.z * invN - mu * mu;
        xn[2] = (y.z - mu) * rsqrtf(var + 1e-5f) * g.z + b.z;
        mu = sm.w * invN; var = sq.w * invN - mu * mu;
        xn[3] = (y.w - mu) * rsqrtf(var + 1e-5f) * g.w + b.w;
    }

    float ss = xn[0] * xn[0] + xn[1] * xn[1] + xn[2] * xn[2] + xn[3] * xn[3];
#pragma unroll
    for (int o = 16; o > 0; o >>= 1)
        ss += __shfl_xor_sync(0xffffffffu, ss, o);

    const float inv = 1.f / (sqrtf(ss) + 1e-6f);
    float4 o4;
    o4.x = xn[0] * inv; o4.y = xn[1] * inv; o4.z = xn[2] * inv; o4.w = xn[3] * inv;
    *(float4*)(Xo + (size_t)w * D + c) = o4;
}

// ---------------------------------------------------------------------------
// Launch
// ---------------------------------------------------------------------------
extern "C" void kernel_launch(void* const* d_in, const int* in_sizes, int n_in,
                              void* d_out, int out_size)
{
    const float* X    = (const float*)d_in[0];
    const int*   n0   = (const int*)  d_in[1];
    const int*   n1   = (const int*)  d_in[2];
    const float* Wa0  = (const float*)d_in[3];
    const float* ba0  = (const float*)d_in[4];
    const float* Wa1  = (const float*)d_in[5];
    const float* ba1  = (const float*)d_in[6];
    const float* W0   = (const float*)d_in[7];
    const float* b0   = (const float*)d_in[8];
    const float* W1   = (const float*)d_in[9];
    const float* b1   = (const float*)d_in[10];
    const float* gmm  = (const float*)d_in[11];
    const float* beta = (const float*)d_in[12];

    const int N = in_sizes[0] / D;
    const int S = in_sizes[1] / N;

    float *A, *B, *C;
    cudaGetSymbolAddress((void**)&A, g_bufA);
    cudaGetSymbolAddress((void**)&B, g_bufB);
    cudaGetSymbolAddress((void**)&C, g_bufC);
    __half* Zh = (__half*)C;   // fp16 gather table aliases g_bufC

    const int gemm_blocks   = (N + BM - 1) / BM;
    const int warp_blocks   = (N + 7) / 8;     // bn_norm: warp per row
    const int gather_blocks = (N + 15) / 16;   // gather: half-warp per node

    // ---- Layer 0 ----
    // Z0h = relu(X @ Wa0 + ba0) in fp16; extra block zeroes BN accumulators.
    gemm_f16_kernel<1, 1><<<gemm_blocks + 1, 256, SMEM_BYTES>>>(X, nullptr, Wa0, ba0, Zh, N, D, 1);
    // agg0 = max_s Z0h[neigh0]
    gathermax_h_kernel<<<gather_blocks, 256>>>(Zh, n0, B, N, S);
    // Y = relu([X, agg0] @ W0 + b0); epilogue accumulates BN column stats.
    gemm_f16_kernel<2, 0><<<gemm_blocks, 256, SMEM_BYTES>>>(X, B, W0, b0, C, N, 2 * D, 1);
    // BatchNorm + row L2 normalize -> X1 (in A)
    bn_norm_kernel<<<warp_blocks, 256>>>(C, gmm, beta, A, N, 1.f / (float)N);

    // ---- Layer 1 ----
    // Z1h = relu(X1 @ Wa1 + ba1) in fp16 (overwrites Y; bn_norm already done)
    gemm_f16_kernel<0, 1><<<gemm_blocks, 256, SMEM_BYTES>>>(A, nullptr, Wa1, ba1, Zh, N, D, 1);
    // agg1 = max_s Z1h[neigh1]
    gathermax_h_kernel<<<gather_blocks, 256>>>(Zh, n1, B, N, S);
    // out = [X1, agg1] @ W1 + b1   (no activation)
    gemm_f16_kernel<0, 0><<<gemm_blocks, 256, SMEM_BYTES>>>(A, B, W1, b1, (float*)d_out, N, 2 * D, 0);
}